// round 2
// baseline (speedup 1.0000x reference)
#include <cuda_runtime.h>

#define BATCH 4
#define C_LIDAR 128
#define HGT 256
#define WID 256
#define HW (HGT*WID)
#define C_CAM 256
#define HEADS 4
#define DIM_HEAD 32
#define HD 128
#define N_TOK 8192
#define TB 8
#define SCALE 0.17677669529663687f  /* 1/sqrt(32) */

typedef unsigned long long ull;

// scratch (static __device__ allocation is allowed)
__device__ float g_v[(size_t)BATCH * N_TOK * HD];        // 16.8 MB
__device__ float g_s[(size_t)BATCH * HEADS * N_TOK];     // logits
__device__ float g_red[BATCH * HEADS * 2];               // (max, 1/sumexp)

// packed fp32x2 FMA: d = a*b + d  (elementwise on the two fp32 lanes)
__device__ __forceinline__ void ffma2(ull& d, ull a, ull b) {
    asm("fma.rn.f32x2 %0, %1, %2, %0;" : "+l"(d) : "l"(a), "l"(b));
}
__device__ __forceinline__ float ull_hsum(ull v) {
    float lo, hi;
    asm("mov.b64 {%0, %1}, %2;" : "=f"(lo), "=f"(hi) : "l"(v));
    return lo + hi;
}

// ---------------------------------------------------------------------------
// Kernel 1: out = lidar + alpha * out_bias[c]   (dense, float4)
// ---------------------------------------------------------------------------
__global__ void bias_copy_kernel(const float* __restrict__ lidar,
                                 const float* __restrict__ out_bias,
                                 const float* __restrict__ alpha_p,
                                 float* __restrict__ out) {
    int i4 = blockIdx.x * blockDim.x + threadIdx.x;   // float4 index
    int c = (i4 >> 14) & 127;                         // (i4*4 / 65536) % 128
    float alpha = __ldg(alpha_p);
    float bb = alpha * __ldg(&out_bias[c]);
    float4 v = ((const float4*)lidar)[i4];
    v.x += bb; v.y += bb; v.z += bb; v.w += bb;
    ((float4*)out)[i4] = v;
}

// ---------------------------------------------------------------------------
// Kernel 2: per-token k, v, q-gather, logit.
// Block = 128 threads, TB=8 tokens. Thread owns channels (c0, c0+64) for
// 4 tokens (jb..jb+3). All dot products in packed f32x2.
// ---------------------------------------------------------------------------
__global__ __launch_bounds__(128) void token_fwd_kernel(
    const float* __restrict__ lidar, const float* __restrict__ tok,
    const int* __restrict__ idx, const float* __restrict__ q_w,
    const float* __restrict__ q_bias, const float* __restrict__ k_w,
    const float* __restrict__ v_w) {
    __shared__ __align__(16) float s_tok[TB][C_CAM];   // 8 KB
    __shared__ __align__(16) float s_x[TB][C_LIDAR];   // 4 KB

    int b = blockIdx.y;
    int t0 = blockIdx.x * TB;
    int tid = threadIdx.x;

    // load TB token feature rows (coalesced float4)
    const float4* tok4 = (const float4*)(tok + ((size_t)b * N_TOK + t0) * C_CAM);
    float4* stok4 = (float4*)&s_tok[0][0];
#pragma unroll
    for (int p = 0; p < (TB * C_CAM / 4) / 128; p++)
        stok4[p * 128 + tid] = tok4[p * 128 + tid];

    // gather lidar feature vectors at token positions (1 sector per element)
#pragma unroll
    for (int j = 0; j < TB; j++) {
        int ii = idx[((size_t)b * N_TOK + t0 + j) * 2 + 0];
        int jj = idx[((size_t)b * N_TOK + t0 + j) * 2 + 1];
        ii = min(max(ii, 0), HGT - 1);
        jj = min(max(jj, 0), WID - 1);
        s_x[j][tid] = __ldg(&lidar[(((size_t)b * C_LIDAR + tid) * HGT + ii) * WID + jj]);
    }
    __syncthreads();

    int c0 = tid & 63;
    int c1 = c0 + 64;
    int jb = (tid >> 6) * 4;     // token half: 0..3 or 4..7

    ull acc_k[2][4], acc_v[2][4], acc_q[2][4];
#pragma unroll
    for (int s = 0; s < 2; s++)
#pragma unroll
        for (int j = 0; j < 4; j++) { acc_k[s][j] = 0ull; acc_v[s][j] = 0ull; acc_q[s][j] = 0ull; }

    // k, v: 256-dim dots
    const ulonglong2* kw0 = (const ulonglong2*)(k_w + (size_t)c0 * C_CAM);
    const ulonglong2* kw1 = (const ulonglong2*)(k_w + (size_t)c1 * C_CAM);
    const ulonglong2* vw0 = (const ulonglong2*)(v_w + (size_t)c0 * C_CAM);
    const ulonglong2* vw1 = (const ulonglong2*)(v_w + (size_t)c1 * C_CAM);
#pragma unroll 4
    for (int i4 = 0; i4 < C_CAM / 4; i4++) {
        ulonglong2 a0 = kw0[i4], a1 = kw1[i4];
        ulonglong2 b0 = vw0[i4], b1 = vw1[i4];
#pragma unroll
        for (int j = 0; j < 4; j++) {
            ulonglong2 t = *(const ulonglong2*)&s_tok[jb + j][i4 * 4];
            ffma2(acc_k[0][j], a0.x, t.x); ffma2(acc_k[0][j], a0.y, t.y);
            ffma2(acc_k[1][j], a1.x, t.x); ffma2(acc_k[1][j], a1.y, t.y);
            ffma2(acc_v[0][j], b0.x, t.x); ffma2(acc_v[0][j], b0.y, t.y);
            ffma2(acc_v[1][j], b1.x, t.x); ffma2(acc_v[1][j], b1.y, t.y);
        }
    }
    // q: 128-dim dots on gathered lidar features
    const ulonglong2* qw0 = (const ulonglong2*)(q_w + (size_t)c0 * C_LIDAR);
    const ulonglong2* qw1 = (const ulonglong2*)(q_w + (size_t)c1 * C_LIDAR);
#pragma unroll 4
    for (int i4 = 0; i4 < C_LIDAR / 4; i4++) {
        ulonglong2 a0 = qw0[i4], a1 = qw1[i4];
#pragma unroll
        for (int j = 0; j < 4; j++) {
            ulonglong2 x = *(const ulonglong2*)&s_x[jb + j][i4 * 4];
            ffma2(acc_q[0][j], a0.x, x.x); ffma2(acc_q[0][j], a0.y, x.y);
            ffma2(acc_q[1][j], a1.x, x.x); ffma2(acc_q[1][j], a1.y, x.y);
        }
    }

    float qb0 = __ldg(&q_bias[c0]);
    float qb1 = __ldg(&q_bias[c1]);
    int h0 = c0 >> 5;        // uniform per warp: warp0/2 -> 0, warp1/3 -> 1
    int h1 = h0 + 2;
    int lane = tid & 31;

#pragma unroll
    for (int j = 0; j < 4; j++) {
        int t = t0 + jb + j;
        float k0 = ull_hsum(acc_k[0][j]);
        float k1 = ull_hsum(acc_k[1][j]);
        float v0 = ull_hsum(acc_v[0][j]);
        float v1 = ull_hsum(acc_v[1][j]);
        float p0 = (ull_hsum(acc_q[0][j]) + qb0) * k0;
        float p1 = (ull_hsum(acc_q[1][j]) + qb1) * k1;
#pragma unroll
        for (int off = 16; off > 0; off >>= 1) {
            p0 += __shfl_down_sync(0xffffffffu, p0, off);
            p1 += __shfl_down_sync(0xffffffffu, p1, off);
        }
        if (lane == 0) {
            g_s[((size_t)b * HEADS + h0) * N_TOK + t] = p0 * SCALE;
            g_s[((size_t)b * HEADS + h1) * N_TOK + t] = p1 * SCALE;
        }
        // v store: lane -> consecutive channels (coalesced 128B segments)
        float* gv = g_v + ((size_t)(b * N_TOK + t)) * HD;
        gv[c0] = v0;
        gv[c1] = v1;
    }
}

// ---------------------------------------------------------------------------
// Kernel 3: per (b,h): max + sum(exp) over 8192 logits
// ---------------------------------------------------------------------------
__global__ void softmax_reduce_kernel() {
    int bh = blockIdx.x;  // 0..15
    const float* s = g_s + (size_t)bh * N_TOK;
    __shared__ float red[512];
    int tid = threadIdx.x;

    float m = -1e30f;
    for (int i = tid; i < N_TOK; i += 512) m = fmaxf(m, s[i]);
    red[tid] = m;
    __syncthreads();
#pragma unroll
    for (int st = 256; st > 0; st >>= 1) {
        if (tid < st) red[tid] = fmaxf(red[tid], red[tid + st]);
        __syncthreads();
    }
    m = red[0];
    __syncthreads();

    float sum = 0.f;
    for (int i = tid; i < N_TOK; i += 512) sum += expf(s[i] - m);
    red[tid] = sum;
    __syncthreads();
#pragma unroll
    for (int st = 256; st > 0; st >>= 1) {
        if (tid < st) red[tid] += red[tid + st];
        __syncthreads();
    }
    if (tid == 0) {
        g_red[bh * 2 + 0] = m;
        g_red[bh * 2 + 1] = 1.0f / red[0];
    }
}

// ---------------------------------------------------------------------------
// Kernel 4: a = softmax*gate*alpha; fused = a*v; out-proj (f32x2, 2ch/thread);
// atomic scatter into out.
// ---------------------------------------------------------------------------
__global__ __launch_bounds__(128) void scatter_kernel(
    const int* __restrict__ idx, const float* __restrict__ gate,
    const float* __restrict__ alpha_p, const float* __restrict__ out_w,
    float* __restrict__ out) {
    __shared__ __align__(16) float s_f[TB][HD];
    __shared__ float s_a[TB][HEADS];
    __shared__ int s_ij[TB];

    int b = blockIdx.y;
    int t0 = blockIdx.x * TB;
    int tid = threadIdx.x;

    if (tid < TB * HEADS) {
        int j = tid / HEADS, h = tid % HEADS;
        int bh = b * HEADS + h;
        float m = g_red[bh * 2 + 0];
        float inv = g_red[bh * 2 + 1];
        float sv = g_s[(size_t)bh * N_TOK + t0 + j];
        float alpha = __ldg(alpha_p);
        s_a[j][h] = expf(sv - m) * inv * __ldg(&gate[(size_t)b * N_TOK + t0 + j]) * alpha;
    }
    if (tid < TB) {
        int ii = idx[((size_t)b * N_TOK + t0 + tid) * 2 + 0];
        int jj = idx[((size_t)b * N_TOK + t0 + tid) * 2 + 1];
        ii = min(max(ii, 0), HGT - 1);
        jj = min(max(jj, 0), WID - 1);
        s_ij[tid] = ii * WID + jj;
    }
    __syncthreads();

    // fused = a[head]*v  (alpha folded into a)
    {
        int hd = tid, h = tid >> 5;
#pragma unroll
        for (int j = 0; j < TB; j++)
            s_f[j][hd] = s_a[j][h] * g_v[((size_t)(b * N_TOK + t0 + j)) * HD + hd];
    }
    __syncthreads();

    // out-projection: thread owns channels (c0, c0+64) for 4 tokens
    int c0 = tid & 63;
    int c1 = c0 + 64;
    int jb = (tid >> 6) * 4;

    ull acc[2][4];
#pragma unroll
    for (int s = 0; s < 2; s++)
#pragma unroll
        for (int j = 0; j < 4; j++) acc[s][j] = 0ull;

    const ulonglong2* ow0 = (const ulonglong2*)(out_w + (size_t)c0 * HD);
    const ulonglong2* ow1 = (const ulonglong2*)(out_w + (size_t)c1 * HD);
#pragma unroll 4
    for (int i4 = 0; i4 < HD / 4; i4++) {
        ulonglong2 w0 = ow0[i4], w1 = ow1[i4];
#pragma unroll
        for (int j = 0; j < 4; j++) {
            ulonglong2 f = *(const ulonglong2*)&s_f[jb + j][i4 * 4];
            ffma2(acc[0][j], w0.x, f.x); ffma2(acc[0][j], w0.y, f.y);
            ffma2(acc[1][j], w1.x, f.x); ffma2(acc[1][j], w1.y, f.y);
        }
    }
#pragma unroll
    for (int j = 0; j < 4; j++) {
        int pos = s_ij[jb + j];
        atomicAdd(&out[((size_t)b * C_LIDAR + c0) * HW + pos], ull_hsum(acc[0][j]));
        atomicAdd(&out[((size_t)b * C_LIDAR + c1) * HW + pos], ull_hsum(acc[1][j]));
    }
}

// ---------------------------------------------------------------------------
extern "C" void kernel_launch(void* const* d_in, const int* in_sizes, int n_in,
                              void* d_out, int out_size) {
    const float* lidar    = (const float*)d_in[0];
    const float* tok      = (const float*)d_in[1];
    const int*   idx      = (const int*)  d_in[2];
    const float* gate     = (const float*)d_in[3];
    const float* alpha    = (const float*)d_in[4];
    const float* q_w      = (const float*)d_in[5];
    const float* q_bias   = (const float*)d_in[6];
    const float* k_w      = (const float*)d_in[7];
    const float* v_w      = (const float*)d_in[8];
    const float* out_w    = (const float*)d_in[9];
    const float* out_bias = (const float*)d_in[10];
    float* out = (float*)d_out;

    bias_copy_kernel<<<32768, 256>>>(lidar, out_bias, alpha, out);

    dim3 g(N_TOK / TB, BATCH);
    token_fwd_kernel<<<g, 128>>>(lidar, tok, idx, q_w, q_bias, k_w, v_w);
    softmax_reduce_kernel<<<16, 512>>>();
    scatter_kernel<<<g, 128>>>(idx, gate, alpha, out_w, out);
}

// round 3
// speedup vs baseline: 2.4182x; 2.4182x over previous
#include <cuda_runtime.h>

#define BATCH 4
#define C_LIDAR 128
#define HGT 256
#define WID 256
#define HW (HGT*WID)
#define C_CAM 256
#define HEADS 4
#define DIM_HEAD 32
#define HD 128
#define N_TOK 8192
#define TB 16
#define SCALE 0.17677669529663687f  /* 1/sqrt(32) */

// ---------------------------------------------------------------------------
// scratch (__device__ globals — allocation-free)
// ---------------------------------------------------------------------------
__device__ float g_v[(size_t)BATCH * N_TOK * HD];        // 16.8 MB
__device__ float g_s[(size_t)BATCH * HEADS * N_TOK];     // logits
__device__ float g_red[BATCH * HEADS * 2];               // (max, 1/sumexp)

// d-major packed weights: wT4[d4*128 + c] = (w[c][4*d4+0..3])
__device__ float4 g_kwT4[(C_CAM / 4) * HD];              // 64*128
__device__ float4 g_vwT4[(C_CAM / 4) * HD];              // 64*128
__device__ float4 g_qwT4[(C_LIDAR / 4) * HD];            // 32*128
__device__ float4 g_owT4[(HD / 4) * C_LIDAR];            // 32*128

// ---------------------------------------------------------------------------
// Kernel 0: weight transpose/pack (runs every launch; ~1.3 MB of traffic)
// slot layout: [0,8192) k  [8192,16384) v  [16384,20480) q  [20480,24576) o
// ---------------------------------------------------------------------------
__global__ void transpose_weights_kernel(const float* __restrict__ kw,
                                         const float* __restrict__ vw,
                                         const float* __restrict__ qw,
                                         const float* __restrict__ ow) {
    int g = blockIdx.x * blockDim.x + threadIdx.x;
    if (g < 8192) {
        int d4 = g >> 7, c = g & 127;
        const float* p = kw + (size_t)c * C_CAM + 4 * d4;
        g_kwT4[g] = make_float4(p[0], p[1], p[2], p[3]);
    } else if (g < 16384) {
        int l = g - 8192, d4 = l >> 7, c = l & 127;
        const float* p = vw + (size_t)c * C_CAM + 4 * d4;
        g_vwT4[l] = make_float4(p[0], p[1], p[2], p[3]);
    } else if (g < 20480) {
        int l = g - 16384, d4 = l >> 7, c = l & 127;
        const float* p = qw + (size_t)c * C_LIDAR + 4 * d4;
        g_qwT4[l] = make_float4(p[0], p[1], p[2], p[3]);
    } else if (g < 24576) {
        int l = g - 20480, d4 = l >> 7, c = l & 127;
        const float* p = ow + (size_t)c * HD + 4 * d4;
        g_owT4[l] = make_float4(p[0], p[1], p[2], p[3]);
    }
}

// ---------------------------------------------------------------------------
// Kernel 1: out = lidar + alpha * out_bias[c]   (dense, float4)
// ---------------------------------------------------------------------------
__global__ void bias_copy_kernel(const float* __restrict__ lidar,
                                 const float* __restrict__ out_bias,
                                 const float* __restrict__ alpha_p,
                                 float* __restrict__ out) {
    int i4 = blockIdx.x * blockDim.x + threadIdx.x;   // float4 index
    int c = (i4 >> 14) & 127;                         // (i4*4 / 65536) % 128
    float alpha = __ldg(alpha_p);
    float bb = alpha * __ldg(&out_bias[c]);
    float4 v = ((const float4*)lidar)[i4];
    v.x += bb; v.y += bb; v.z += bb; v.w += bb;
    ((float4*)out)[i4] = v;
}

// ---------------------------------------------------------------------------
// Kernel 2: per-token q-gather, k, v, logit.  Block = 128 threads = 128
// channels; TB=16 tokens per block. Weight loads are COALESCED (d-major),
// activations are uniform LDS.128 broadcasts. Warp h owns head h's channels.
// ---------------------------------------------------------------------------
__global__ __launch_bounds__(128) void token_fwd_kernel(
    const float* __restrict__ lidar, const float* __restrict__ tok,
    const int* __restrict__ idx, const float* __restrict__ q_bias) {
    __shared__ __align__(16) float4 s_tok[TB][C_CAM / 4];   // 16 KB
    __shared__ __align__(16) float4 s_x[TB][C_LIDAR / 4];   // 8 KB

    int b = blockIdx.y;
    int t0 = blockIdx.x * TB;
    int tid = threadIdx.x;

    // load TB token feature rows (coalesced float4): 16*64 = 1024 float4
    const float4* tok4 = (const float4*)(tok + ((size_t)b * N_TOK + t0) * C_CAM);
    float4* stok4 = &s_tok[0][0];
#pragma unroll
    for (int p = 0; p < (TB * C_CAM / 4) / 128; p++)
        stok4[p * 128 + tid] = tok4[p * 128 + tid];

    // gather lidar feature vectors at token positions (scattered, unavoidable)
#pragma unroll
    for (int j = 0; j < TB; j++) {
        int ii = idx[((size_t)b * N_TOK + t0 + j) * 2 + 0];
        int jj = idx[((size_t)b * N_TOK + t0 + j) * 2 + 1];
        ii = min(max(ii, 0), HGT - 1);
        jj = min(max(jj, 0), WID - 1);
        ((float*)s_x[j])[tid] =
            __ldg(&lidar[(((size_t)b * C_LIDAR + tid) * HGT + ii) * WID + jj]);
    }
    __syncthreads();

    // ---- q pass: 128-dim dots on gathered lidar features ----
    float acc_q[TB];
#pragma unroll
    for (int j = 0; j < TB; j++) acc_q[j] = 0.f;
#pragma unroll 4
    for (int d4 = 0; d4 < C_LIDAR / 4; d4++) {
        float4 w = g_qwT4[d4 * 128 + tid];          // coalesced
#pragma unroll
        for (int j = 0; j < TB; j++) {
            float4 x = s_x[j][d4];                   // uniform broadcast
            acc_q[j] += w.x * x.x + w.y * x.y + w.z * x.z + w.w * x.w;
        }
    }

    // ---- k & v pass: 256-dim dots on token features ----
    float acc_k[TB], acc_v[TB];
#pragma unroll
    for (int j = 0; j < TB; j++) { acc_k[j] = 0.f; acc_v[j] = 0.f; }
#pragma unroll 4
    for (int d4 = 0; d4 < C_CAM / 4; d4++) {
        float4 wk = g_kwT4[d4 * 128 + tid];         // coalesced
        float4 wv = g_vwT4[d4 * 128 + tid];         // coalesced
#pragma unroll
        for (int j = 0; j < TB; j++) {
            float4 t = s_tok[j][d4];                 // uniform broadcast
            acc_k[j] += wk.x * t.x + wk.y * t.y + wk.z * t.z + wk.w * t.w;
            acc_v[j] += wv.x * t.x + wv.y * t.y + wv.z * t.z + wv.w * t.w;
        }
    }

    float qb = __ldg(&q_bias[tid]);
    int h = tid >> 5;         // warp id == head id
    int lane = tid & 31;
#pragma unroll
    for (int j = 0; j < TB; j++) {
        int t = t0 + j;
        float p = (acc_q[j] + qb) * acc_k[j];
#pragma unroll
        for (int off = 16; off > 0; off >>= 1)
            p += __shfl_down_sync(0xffffffffu, p, off);
        if (lane == 0)
            g_s[((size_t)b * HEADS + h) * N_TOK + t] = p * SCALE;
        g_v[((size_t)(b * N_TOK + t)) * HD + tid] = acc_v[j];  // coalesced
    }
}

// ---------------------------------------------------------------------------
// Kernel 3: per (b,h): max + sum(exp) over 8192 logits
// ---------------------------------------------------------------------------
__global__ void softmax_reduce_kernel() {
    int bh = blockIdx.x;  // 0..15
    const float* s = g_s + (size_t)bh * N_TOK;
    __shared__ float red[512];
    int tid = threadIdx.x;

    float m = -1e30f;
    for (int i = tid; i < N_TOK; i += 512) m = fmaxf(m, s[i]);
    red[tid] = m;
    __syncthreads();
#pragma unroll
    for (int st = 256; st > 0; st >>= 1) {
        if (tid < st) red[tid] = fmaxf(red[tid], red[tid + st]);
        __syncthreads();
    }
    m = red[0];
    __syncthreads();

    float sum = 0.f;
    for (int i = tid; i < N_TOK; i += 512) sum += expf(s[i] - m);
    red[tid] = sum;
    __syncthreads();
#pragma unroll
    for (int st = 256; st > 0; st >>= 1) {
        if (tid < st) red[tid] += red[tid + st];
        __syncthreads();
    }
    if (tid == 0) {
        g_red[bh * 2 + 0] = m;
        g_red[bh * 2 + 1] = 1.0f / red[0];
    }
}

// ---------------------------------------------------------------------------
// Kernel 4: a = softmax*gate*alpha; fused = a*v; out-proj with coalesced
// d-major weights; atomic scatter into out.
// ---------------------------------------------------------------------------
__global__ __launch_bounds__(128) void scatter_kernel(
    const int* __restrict__ idx, const float* __restrict__ gate,
    const float* __restrict__ alpha_p, float* __restrict__ out) {
    __shared__ __align__(16) float4 s_f[TB][HD / 4];   // 8 KB
    __shared__ float s_a[TB][HEADS];
    __shared__ int s_ij[TB];

    int b = blockIdx.y;
    int t0 = blockIdx.x * TB;
    int tid = threadIdx.x;

    if (tid < TB * HEADS) {
        int j = tid / HEADS, h = tid % HEADS;
        int bh = b * HEADS + h;
        float m = g_red[bh * 2 + 0];
        float inv = g_red[bh * 2 + 1];
        float sv = g_s[(size_t)bh * N_TOK + t0 + j];
        float alpha = __ldg(alpha_p);
        s_a[j][h] = expf(sv - m) * inv * __ldg(&gate[(size_t)b * N_TOK + t0 + j]) * alpha;
    }
    if (tid < TB) {
        int ii = idx[((size_t)b * N_TOK + t0 + tid) * 2 + 0];
        int jj = idx[((size_t)b * N_TOK + t0 + tid) * 2 + 1];
        ii = min(max(ii, 0), HGT - 1);
        jj = min(max(jj, 0), WID - 1);
        s_ij[tid] = ii * WID + jj;
    }
    __syncthreads();

    // fused = a[head]*v  (alpha folded into a); coalesced g_v reads
    {
        int h = tid >> 5;
#pragma unroll
        for (int j = 0; j < TB; j++)
            ((float*)s_f[j])[tid] =
                s_a[j][h] * g_v[((size_t)(b * N_TOK + t0 + j)) * HD + tid];
    }
    __syncthreads();

    // out-projection: thread tid owns output channel c = tid
    float acc[TB];
#pragma unroll
    for (int j = 0; j < TB; j++) acc[j] = 0.f;
#pragma unroll 4
    for (int hd4 = 0; hd4 < HD / 4; hd4++) {
        float4 w = g_owT4[hd4 * 128 + tid];          // coalesced
#pragma unroll
        for (int j = 0; j < TB; j++) {
            float4 f = s_f[j][hd4];                   // uniform broadcast
            acc[j] += w.x * f.x + w.y * f.y + w.z * f.z + w.w * f.w;
        }
    }
#pragma unroll
    for (int j = 0; j < TB; j++)
        atomicAdd(&out[((size_t)b * C_LIDAR + tid) * HW + s_ij[j]], acc[j]);
}

// ---------------------------------------------------------------------------
extern "C" void kernel_launch(void* const* d_in, const int* in_sizes, int n_in,
                              void* d_out, int out_size) {
    const float* lidar    = (const float*)d_in[0];
    const float* tok      = (const float*)d_in[1];
    const int*   idx      = (const int*)  d_in[2];
    const float* gate     = (const float*)d_in[3];
    const float* alpha    = (const float*)d_in[4];
    const float* q_w      = (const float*)d_in[5];
    const float* q_bias   = (const float*)d_in[6];
    const float* k_w      = (const float*)d_in[7];
    const float* v_w      = (const float*)d_in[8];
    const float* out_w    = (const float*)d_in[9];
    const float* out_bias = (const float*)d_in[10];
    float* out = (float*)d_out;

    transpose_weights_kernel<<<96, 256>>>(k_w, v_w, q_w, out_w);
    bias_copy_kernel<<<32768, 256>>>(lidar, out_bias, alpha, out);

    dim3 g(N_TOK / TB, BATCH);
    token_fwd_kernel<<<g, 128>>>(lidar, tok, idx, q_bias);
    softmax_reduce_kernel<<<16, 512>>>();
    scatter_kernel<<<g, 128>>>(idx, gate, alpha, out);
}